// round 1
// baseline (speedup 1.0000x reference)
#include <cuda_runtime.h>
#include <cstdint>
#include <cstddef>

#define D 128
#define NVEC 65536                 // 16 * 64 * 64
#define CBT_FLOATS 65280           // 510 * 128
#define OUT_TENSOR 67108864LL      // 8*16*128*64*64

// -------- scratch (static device globals; no runtime allocation) --------
__device__ float g_cbT[CBT_FLOATS];          // per level: cbT[c * sz + j], levels packed
__device__ float g_cnorm[768];               // ||c||^2, padded per level (offsets below)
__device__ unsigned long long g_idx[NVEC];   // 8 packed uint8 indices per vector
__device__ float g_lsum[8];                  // per-level sum of min distances

// stage s (0-based) uses weight rows c_rows[2s], c_rows[2s+1]
__constant__ int c_rows[16] = {0,1, 3,4, 4,5, 5,6, 6,7, 7,8, 8,9, 9,10};
// padded (16B-aligned) start offset of each level's norms inside g_cnorm
__constant__ int c_pad[8] = {0, 4, 8, 16, 48, 112, 240, 496};
__constant__ float c_coef[8] = {1.5f, 1.2f, 1.0f, 0.9f, 0.82f, 0.69f, 0.65f, 0.56f};

// ---------------------------------------------------------------------------
// Kernel 0: build transposed codebooks + squared norms; zero loss accumulators.
// One block per codeword (510 blocks, 128 threads = one channel each).
// ---------------------------------------------------------------------------
__global__ void build_kernel(const float* __restrict__ w) {
    int k  = blockIdx.x;              // 0..509 global codeword id
    int li = 30 - __clz(k + 2);       // level index 0..7  (level L = li+1)
    int L  = li + 1;
    int sz = 1 << L;
    int j  = k - (sz - 2);            // codeword index within level
    int c  = threadIdx.x;             // channel 0..127

    float val = 0.f;
    for (int s = 0; s < L; s++) {
        int bit = (j >> (L - 1 - s)) & 1;
        val += w[c_rows[2 * s + bit] * D + c];
    }
    g_cbT[(sz - 2) * D + c * sz + j] = val;

    __shared__ float red[128];
    red[c] = val * val;
    __syncthreads();
    #pragma unroll
    for (int o = 64; o > 0; o >>= 1) {
        if (c < o) red[c] += red[c + o];
        __syncthreads();
    }
    if (c == 0) g_cnorm[c_pad[li] + j] = red[0];

    if (blockIdx.x == 0 && c < 8) g_lsum[c] = 0.f;   // reset each launch (graph replay safe)
}

// ---------------------------------------------------------------------------
// Kernel 1: per-vector quantization. Thread-per-vector (coalesced over hw).
// Computes the 16 stage dot products, then all 510 scores via register
// prefix trees. Writes packed indices + accumulates per-level loss sums.
// ---------------------------------------------------------------------------
__global__ void __launch_bounds__(256, 2)
quant_kernel(const float* __restrict__ inp, const float* __restrict__ w) {
    __shared__ float s_bv[16][128];   // base vectors pre-scaled by -2
    __shared__ float sC[768];         // padded codeword norms
    __shared__ float s_loss[8];

    int tid = threadIdx.x;
    for (int i = tid; i < 16 * 128; i += 256) {
        int s = i >> 7, c = i & 127;
        s_bv[s][c] = -2.0f * w[c_rows[s] * D + c];
    }
    for (int i = tid; i < 752; i += 256) sC[i] = g_cnorm[i];
    if (tid < 8) s_loss[tid] = 0.f;
    __syncthreads();

    int vec = blockIdx.x * 256 + tid;                     // 0..65535
    const float* xp = inp + ((size_t)(vec >> 12) << 19) + (vec & 4095);

    // ---- 16 dot products p[s] = -2 * x . v_s  (+ ||x||^2) ----
    float acc[16];
    #pragma unroll
    for (int s = 0; s < 16; s++) acc[s] = 0.f;
    float xn = 0.f;

    #pragma unroll 4
    for (int c4 = 0; c4 < 32; c4++) {
        float x0 = xp[(4 * c4 + 0) * 4096];
        float x1 = xp[(4 * c4 + 1) * 4096];
        float x2 = xp[(4 * c4 + 2) * 4096];
        float x3 = xp[(4 * c4 + 3) * 4096];
        xn = fmaf(x0, x0, xn); xn = fmaf(x1, x1, xn);
        xn = fmaf(x2, x2, xn); xn = fmaf(x3, x3, xn);
        #pragma unroll
        for (int s = 0; s < 16; s++) {
            float4 bq = reinterpret_cast<const float4*>(&s_bv[s][0])[c4];
            acc[s] = fmaf(x0, bq.x, acc[s]);
            acc[s] = fmaf(x1, bq.y, acc[s]);
            acc[s] = fmaf(x2, bq.z, acc[s]);
            acc[s] = fmaf(x3, bq.w, acc[s]);
        }
    }

    float* p = acc;   // p[2s+b] = -2 x.v_{s,b}

    // ---- prefix trees: A side (stages 0..3), B side (stages 4..7) ----
    float A2[4], A3[8], A4[16], B2[4], B3[8], B4[16];
    #pragma unroll
    for (int j = 0; j < 4;  j++) A2[j] = p[j >> 1] + p[2 + (j & 1)];
    #pragma unroll
    for (int j = 0; j < 8;  j++) A3[j] = A2[j >> 1] + p[4 + (j & 1)];
    #pragma unroll
    for (int j = 0; j < 16; j++) A4[j] = A3[j >> 1] + p[6 + (j & 1)];
    #pragma unroll
    for (int j = 0; j < 4;  j++) B2[j] = p[8 + (j >> 1)] + p[10 + (j & 1)];
    #pragma unroll
    for (int j = 0; j < 8;  j++) B3[j] = B2[j >> 1] + p[12 + (j & 1)];
    #pragma unroll
    for (int j = 0; j < 16; j++) B4[j] = B3[j >> 1] + p[14 + (j & 1)];

    const float INF = __int_as_float(0x7f800000);
    float m[8]; int mi[8];
    #pragma unroll
    for (int l = 0; l < 8; l++) { m[l] = INF; mi[l] = 0; }

    // strict '<' keeps the FIRST minimum (matches jnp.argmin tie-break)
    #pragma unroll
    for (int j = 0; j < 2;   j++) { float s = p[j]            + sC[0   + j]; if (s < m[0]) { m[0] = s; mi[0] = j; } }
    #pragma unroll
    for (int j = 0; j < 4;   j++) { float s = A2[j]           + sC[4   + j]; if (s < m[1]) { m[1] = s; mi[1] = j; } }
    #pragma unroll
    for (int j = 0; j < 8;   j++) { float s = A3[j]           + sC[8   + j]; if (s < m[2]) { m[2] = s; mi[2] = j; } }
    #pragma unroll
    for (int j = 0; j < 16;  j++) { float s = A4[j]           + sC[16  + j]; if (s < m[3]) { m[3] = s; mi[3] = j; } }
    #pragma unroll
    for (int j = 0; j < 32;  j++) { float s = A4[j >> 1] + p[8 + (j & 1)]  + sC[48  + j]; if (s < m[4]) { m[4] = s; mi[4] = j; } }
    #pragma unroll
    for (int j = 0; j < 64;  j++) { float s = A4[j >> 2] + B2[j & 3]       + sC[112 + j]; if (s < m[5]) { m[5] = s; mi[5] = j; } }
    #pragma unroll
    for (int j = 0; j < 128; j++) { float s = A4[j >> 3] + B3[j & 7]       + sC[240 + j]; if (s < m[6]) { m[6] = s; mi[6] = j; } }
    #pragma unroll
    for (int j = 0; j < 256; j++) { float s = A4[j >> 4] + B4[j & 15]      + sC[496 + j]; if (s < m[7]) { m[7] = s; mi[7] = j; } }

    // ---- pack indices ----
    unsigned long long pk = 0;
    #pragma unroll
    for (int l = 0; l < 8; l++) pk |= ((unsigned long long)(unsigned)mi[l]) << (8 * l);
    g_idx[vec] = pk;

    // ---- loss: dist_min = ||x||^2 + score_min; warp reduce then atomics ----
    int lane = tid & 31;
    #pragma unroll
    for (int l = 0; l < 8; l++) {
        float v = xn + m[l];
        #pragma unroll
        for (int o = 16; o; o >>= 1) v += __shfl_xor_sync(0xffffffffu, v, o);
        if (lane == 0) atomicAdd(&s_loss[l], v);
    }
    __syncthreads();
    if (tid < 8) atomicAdd(&g_lsum[tid], s_loss[tid]);
}

// ---------------------------------------------------------------------------
// Kernel 2: output writer. One CTA per (level, batch): 128 CTAs = one wave.
// Transposed codebook lives in smem -> low-conflict LDS gather; coalesced
// STG.128 stores of the full 268 MB output tensor.
// ---------------------------------------------------------------------------
__global__ void __launch_bounds__(512, 1)
scatter_kernel(float* __restrict__ out) {
    extern __shared__ float sm[];
    int level = blockIdx.x >> 4;     // 0..7
    int b     = blockIdx.x & 15;     // 0..15
    int sz    = 2 << level;          // codebook size 2..256
    int n     = sz << 7;             // sz * 128 floats
    int tid   = threadIdx.x;

    float*   scb  = sm;                                // cbT for this level
    uint8_t* sidx = (uint8_t*)(sm + n);                // 4096 indices

    const float* src = g_cbT + ((sz - 2) << 7);
    for (int i = tid; i < n; i += 512) scb[i] = src[i];

    const unsigned long long* gi = g_idx + ((size_t)b << 12);
    int sh = level << 3;
    for (int i = tid; i < 4096; i += 512) sidx[i] = (uint8_t)(gi[i] >> sh);
    __syncthreads();

    // each thread writes 2 float4 per channel: hw = 4*tid and 2048 + 4*tid
    int o0 = sidx[4 * tid + 0], o1 = sidx[4 * tid + 1];
    int o2 = sidx[4 * tid + 2], o3 = sidx[4 * tid + 3];
    int o4 = sidx[2048 + 4 * tid + 0], o5 = sidx[2048 + 4 * tid + 1];
    int o6 = sidx[2048 + 4 * tid + 2], o7 = sidx[2048 + 4 * tid + 3];

    float* ob = out + ((size_t)blockIdx.x << 19) + (tid << 2);
    const float* row = scb;
    #pragma unroll 4
    for (int c = 0; c < 128; c++) {
        float4 v0 = make_float4(row[o0], row[o1], row[o2], row[o3]);
        float4 v1 = make_float4(row[o4], row[o5], row[o6], row[o7]);
        *reinterpret_cast<float4*>(ob)        = v0;
        *reinterpret_cast<float4*>(ob + 2048) = v1;
        row += sz;
        ob  += 4096;
    }
}

// ---------------------------------------------------------------------------
// Kernel 3: finalize losses.
// ---------------------------------------------------------------------------
__global__ void loss_kernel(float* __restrict__ out, long long out_size) {
    int i = threadIdx.x;
    if (i < 8) {
        long long pos = OUT_TENSOR + i;
        if (pos < out_size)
            out[pos] = (c_coef[i] + 0.4f) * g_lsum[i] * (1.0f / 8388608.0f);
    }
}

// ---------------------------------------------------------------------------
extern "C" void kernel_launch(void* const* d_in, const int* in_sizes, int n_in,
                              void* d_out, int out_size) {
    const float* inp = (const float*)d_in[0];   // (16,128,64,64) f32
    const float* w   = (const float*)d_in[1];   // (256,128) f32
    float* out       = (float*)d_out;

    (void)in_sizes; (void)n_in;

    // 256*512 (cbT floats bytes) + 4096 (idx bytes) = 135168 B dynamic smem
    cudaFuncSetAttribute(scatter_kernel,
                         cudaFuncAttributeMaxDynamicSharedMemorySize, 135168);

    build_kernel<<<510, 128>>>(w);
    quant_kernel<<<256, 256>>>(inp, w);
    scatter_kernel<<<128, 512, 135168>>>(out);
    loss_kernel<<<1, 8>>>(out, (long long)out_size);
}